// round 12
// baseline (speedup 1.0000x reference)
#include <cuda_runtime.h>
#include <cuda_fp16.h>
#include <cstdint>

#define Hdim 256
#define Bdim 2048
#define Tdim 512
#define Vdim 64
#define NB   16          // batches per cluster -> 128 clusters x 2 CTAs = 256 CTAs
#define NOUT 128         // output columns per CTA (half of Hdim)
#define NTH  256         // 8 warps per CTA
#define CLU  2
#define HSTR 264         // h row stride in halfs (528B)
#define PSTR 132         // P row stride in floats (132 mod 32 = 4)
#define ESTR 68          // embT row stride in floats

// ---- shared memory layout (bytes) ----
#define SM_P    0                       // P[64][PSTR] f32 = 33792 (this CTA's 128 cols)
#define SM_H0   33792                   // h buf0: 16 x 264 halfs = 8448 (FULL h)
#define SM_H1   42240                   // h buf1: 8448
#define SM_TOK  50688                   // tokens [512][16] int = 32768 (ends 83456)
#define SM_EMBT 33792                   // transient embT f32 [256][ESTR] = 69632 (ends 103424)
#define SM_MBAR 103424                  // mbarrier
#define SMEM_TOTAL 103552               // x2 CTAs = 207104 <= SM smem capacity

// ---------------------------------------------------------------------------
__device__ __forceinline__ uint32_t smem_u32(const void* p) {
    uint32_t a;
    asm("{ .reg .u64 t; cvta.to.shared.u64 t, %1; cvt.u32.u64 %0, t; }"
        : "=r"(a) : "l"(p));
    return a;
}
__device__ __forceinline__ uint32_t ctarank() {
    uint32_t r;
    asm("mov.u32 %0, %%cluster_ctarank;" : "=r"(r));
    return r;
}
__device__ __forceinline__ uint32_t mapa_peer(uint32_t local_addr, uint32_t peer) {
    uint32_t r;
    asm("mapa.shared::cluster.u32 %0, %1, %2;" : "=r"(r) : "r"(local_addr), "r"(peer));
    return r;
}
__device__ __forceinline__ void st_remote_u32(uint32_t addr, uint32_t v) {
    asm volatile("st.shared::cluster.u32 [%0], %1;" :: "r"(addr), "r"(v) : "memory");
}
#define CLUSTER_SYNC() do { \
    asm volatile("barrier.cluster.arrive.aligned;" ::: "memory"); \
    asm volatile("barrier.cluster.wait.aligned;"   ::: "memory"); } while (0)
// sigmoid via single-MUFU tanh: s = 0.5*tanh(0.5x) + 0.5
__device__ __forceinline__ float sigmoid_t(float x) {
    float t;
    asm("tanh.approx.f32 %0, %1;" : "=f"(t) : "f"(0.5f * x));
    return fmaf(0.5f, t, 0.5f);
}
__device__ __forceinline__ void ffma2(unsigned long long& d,
                                      unsigned long long a, unsigned long long b) {
    asm("fma.rn.f32x2 %0, %1, %2, %0;" : "+l"(d) : "l"(a), "l"(b));
}
__device__ __forceinline__ unsigned long long pack2(float lo, float hi) {
    unsigned long long r;
    asm("mov.b64 %0, {%1, %2};" : "=l"(r) : "f"(lo), "f"(hi));
    return r;
}
__device__ __forceinline__ void mma16816(float* d, const uint32_t* a,
                                         uint32_t b0, uint32_t b1) {
    asm volatile(
        "mma.sync.aligned.m16n8k16.row.col.f32.f16.f16.f32 "
        "{%0,%1,%2,%3}, {%4,%5,%6,%7}, {%8,%9}, {%0,%1,%2,%3};"
        : "+f"(d[0]), "+f"(d[1]), "+f"(d[2]), "+f"(d[3])
        : "r"(a[0]), "r"(a[1]), "r"(a[2]), "r"(a[3]), "r"(b0), "r"(b1));
}
__device__ __forceinline__ void ldmx4(uint32_t& r0, uint32_t& r1,
                                      uint32_t& r2, uint32_t& r3, uint32_t addr) {
    asm volatile(
        "ldmatrix.sync.aligned.m8n8.x4.shared.b16 {%0,%1,%2,%3}, [%4];"
        : "=r"(r0), "=r"(r1), "=r"(r2), "=r"(r3) : "r"(addr));
}
#define MBAR_INIT(mb, c) asm volatile("mbarrier.init.shared.b64 [%0], %1;" \
                                      :: "r"(mb), "r"(c) : "memory")
#define MBAR_ARRIVE(mb)  asm volatile("mbarrier.arrive.shared.b64 _, [%0];" \
                                      :: "r"(mb) : "memory")
#define MBAR_ARRIVE_REMOTE(mb) \
    asm volatile("mbarrier.arrive.release.cluster.shared::cluster.b64 _, [%0];" \
                 :: "r"(mb) : "memory")
__device__ __forceinline__ void mbar_wait_clu(uint32_t mb, uint32_t parity) {
    asm volatile(
        "{ .reg .pred P;\n\t"
        "W_%=:\n\t"
        "mbarrier.try_wait.parity.acquire.cluster.shared::cta.b64 P, [%0], %1, 0x989680;\n\t"
        "@P bra.uni D_%=;\n\t"
        "bra.uni W_%=;\n\t"
        "D_%=: }"
        :: "r"(mb), "r"(parity) : "memory");
}

// ---------------------------------------------------------------------------
// Persistent RNN, 2-CTA cluster per 16-batch group (128 clusters = 256 CTAs,
// 2 CTAs co-resident per SM). CTA rank owns output cols [128r, 128r+128):
// 8 warps, warp w owns 16 cols (2 n8 tiles, breg register-resident). Each
// step: GEMM D[16,128] = h[16,256] x WhT_half, sigmoid, store h' half both
// locally and into the peer's h buffer (st.shared::cluster). Sync: per-CTA
// mbarrier (count 512); EVERY thread arrives on its own barrier (local) AND
// the peer's (remote, release.cluster) each step, waits only its own with
// acquire.cluster -> same skew-free structure as the proven single-barrier
// kernel. The two co-resident CTAs run independent phases, so one CTA's
// sigmoid/sync tail overlaps the other's tensor work.
// ---------------------------------------------------------------------------
__global__ __launch_bounds__(NTH, 2) __cluster_dims__(CLU, 1, 1)
void k_rnn(const int* __restrict__ tokens,
           const float* __restrict__ h0,
           const float* __restrict__ emb,
           const float* __restrict__ W,
           const float* __restrict__ bias,
           float* __restrict__ out) {
    extern __shared__ char smem[];
    const uint32_t sbase = smem_u32(smem);
    float* Psm  = (float*)(smem + SM_P);
    int*   toks = (int*)(smem + SM_TOK);
    const uint32_t mbar = sbase + SM_MBAR;

    const int tid  = threadIdx.x;
    const int wid  = tid >> 5;
    const int lane = tid & 31;
    const int g    = lane >> 2;     // 0..7
    const int r    = lane & 3;      // 0..3
    const uint32_t rank = ctarank();
    const uint32_t peer = rank ^ 1u;
    const int obase = (int)rank * NOUT;
    const int bbase = (blockIdx.x >> 1) * NB;

    // peer smem base (same layout) + peer mbarrier
    const uint32_t rem_sbase = mapa_peer(sbase, peer);
    const uint32_t rem_mbar  = rem_sbase + SM_MBAR;

    // ============== Prologue ==============
    // (1) stage embT[k][v] (transient overlay at SM_EMBT)
    {
        float* embT = (float*)(smem + SM_EMBT);
        for (int idx = tid; idx < Vdim * Hdim; idx += NTH) {
            int v = idx >> 8, k = idx & 255;
            embT[(size_t)k * ESTR + v] = emb[(size_t)v * Hdim + k];
        }
    }
    __syncthreads();
    // (2) P[v][oc] = bias[o] + emb[v,:]·Wx[o,:] for this CTA's 128 cols
    {
        const float* embT = (const float*)(smem + SM_EMBT);
        const int oc = tid & 127;
        const int o_glob = obase + oc;
        const int vg0 = (tid >> 7) * 2;          // 2 threads split the 4 v-groups
        const float bo = bias[o_glob];
        const float4* wrow = (const float4*)(W + (size_t)o_glob * (2 * Hdim));
        for (int vg = vg0; vg < vg0 + 2; ++vg) {
            unsigned long long acc[8];
#pragma unroll
            for (int i = 0; i < 8; ++i) acc[i] = pack2(0.f, 0.f);
            for (int k4 = 0; k4 < Hdim / 4; ++k4) {
                float4 wv = wrow[k4];
#pragma unroll
                for (int kk = 0; kk < 4; ++kk) {
                    int k = k4 * 4 + kk;
                    float w = (kk == 0) ? wv.x : (kk == 1) ? wv.y : (kk == 2) ? wv.z : wv.w;
                    unsigned long long wpair = pack2(w, w);
                    const ulonglong2* ep =
                        (const ulonglong2*)(embT + (size_t)k * ESTR + vg * 16);
                    ulonglong2 e0 = ep[0], e1 = ep[1], e2 = ep[2], e3 = ep[3];
                    ffma2(acc[0], wpair, e0.x); ffma2(acc[1], wpair, e0.y);
                    ffma2(acc[2], wpair, e1.x); ffma2(acc[3], wpair, e1.y);
                    ffma2(acc[4], wpair, e2.x); ffma2(acc[5], wpair, e2.y);
                    ffma2(acc[6], wpair, e3.x); ffma2(acc[7], wpair, e3.y);
                }
            }
#pragma unroll
            for (int i = 0; i < 8; ++i) {
                float lo = __uint_as_float((uint32_t)(acc[i] & 0xffffffffu));
                float hi = __uint_as_float((uint32_t)(acc[i] >> 32));
                int v0 = vg * 16 + 2 * i;
                Psm[(size_t)v0 * PSTR + oc]       = bo + lo;
                Psm[(size_t)(v0 + 1) * PSTR + oc] = bo + hi;
            }
        }
    }
    __syncthreads();     // embT dead; h/tok regions (overlaid) now writable

    // (3) B fragments: warp owns global cols [obase+16w, obase+16w+16)
    uint32_t breg[2][16][2];
#pragma unroll
    for (int nt = 0; nt < 2; ++nt) {
        int n = obase + wid * 16 + nt * 8 + g;
        const float* wr = W + (size_t)n * (2 * Hdim) + Hdim;
#pragma unroll
        for (int c = 0; c < 16; ++c) {
            float2 lo = *(const float2*)&wr[2 * r + 16 * c];
            float2 hi = *(const float2*)&wr[2 * r + 8 + 16 * c];
            __half2 hlo = __floats2half2_rn(lo.x, lo.y);
            __half2 hhi = __floats2half2_rn(hi.x, hi.y);
            breg[nt][c][0] = *(uint32_t*)&hlo;
            breg[nt][c][1] = *(uint32_t*)&hhi;
        }
    }
    // (4) tokens + full h(0) (both CTAs stage the full h tile locally)
    for (int idx = tid; idx < NB * Tdim; idx += NTH) {
        int b = idx >> 9, t = idx & 511;
        toks[t * NB + b] = tokens[(size_t)(bbase + b) * Tdim + t];
    }
    {
        __half* hb = (__half*)(smem + SM_H0);
        for (int idx = tid; idx < NB * Hdim; idx += NTH) {
            int b = idx >> 8, k = idx & 255;
            hb[(size_t)b * HSTR + k] =
                __float2half_rn(h0[(size_t)(bbase + b) * Hdim + k]);
        }
    }
    if (tid == 0) MBAR_INIT(mbar, 2 * NTH);   // 256 local + 256 remote arrives
    __syncthreads();
    CLUSTER_SYNC();                           // both CTAs' mbarriers initialized
    MBAR_ARRIVE(mbar);                        // bootstrap phase 0
    MBAR_ARRIVE_REMOTE(rem_mbar);

    const uint32_t ldm_base =
        (uint32_t)((lane & 15) * (HSTR * 2) + (lane >> 4) * 16);
    const int o0l = wid * 16 + 2 * r;         // local col of this thread
    float* const outcta = out + (size_t)bbase * Hdim + obase;

    // per-thread h-store byte offsets (within a buffer)
    uint32_t hoff[2][2];
#pragma unroll
    for (int nt = 0; nt < 2; ++nt) {
        hoff[nt][0] = (uint32_t)((g * HSTR + obase + o0l + nt * 8) * 2);
        hoff[nt][1] = (uint32_t)(((g + 8) * HSTR + obase + o0l + nt * 8) * 2);
    }

    // ============== Recurrent loop ==============
    for (int t = 0; t < Tdim; ++t) {
        // P/token prefetch (stable regions, pre-wait)
        const int tk0 = toks[t * NB + g];
        const int tk1 = toks[t * NB + g + 8];
        float dA[2][4], dB[2][4];
#pragma unroll
        for (int nt = 0; nt < 2; ++nt) {
            float2 p0 = *(const float2*)&Psm[(size_t)tk0 * PSTR + o0l + nt * 8];
            float2 p1 = *(const float2*)&Psm[(size_t)tk1 * PSTR + o0l + nt * 8];
            dA[nt][0] = p0.x; dA[nt][1] = p0.y;
            dA[nt][2] = p1.x; dA[nt][3] = p1.y;
            dB[nt][0] = 0.f;  dB[nt][1] = 0.f;
            dB[nt][2] = 0.f;  dB[nt][3] = 0.f;
        }

        mbar_wait_clu(mbar, (uint32_t)(t & 1));
        const uint32_t abuf = sbase + ((t & 1) ? SM_H1 : SM_H0) + ldm_base;

        // split chains: dA chunks 0-7, dB chunks 8-15 (interleaved issue)
#pragma unroll
        for (int cc = 0; cc < 8; ++cc) {
            uint32_t a0[4], a1[4];
            ldmx4(a0[0], a0[1], a0[2], a0[3], abuf + (uint32_t)cc * 32);
            ldmx4(a1[0], a1[1], a1[2], a1[3], abuf + (uint32_t)(cc + 8) * 32);
            mma16816(dA[0], a0, breg[0][cc][0], breg[0][cc][1]);
            mma16816(dB[0], a1, breg[0][cc + 8][0], breg[0][cc + 8][1]);
            mma16816(dA[1], a0, breg[1][cc][0], breg[1][cc][1]);
            mma16816(dB[1], a1, breg[1][cc + 8][0], breg[1][cc + 8][1]);
        }

        // epilogue: fold, sigmoid, store h' half locally + to peer, arrive
        const uint32_t hnb = (uint32_t)((t & 1) ? SM_H0 : SM_H1);
        const uint32_t loc_b = sbase + hnb;
        const uint32_t rem_b = rem_sbase + hnb;
        float s[2][4];
#pragma unroll
        for (int nt = 0; nt < 2; ++nt) {
            s[nt][0] = sigmoid_t(dA[nt][0] + dB[nt][0]);
            s[nt][1] = sigmoid_t(dA[nt][1] + dB[nt][1]);
            s[nt][2] = sigmoid_t(dA[nt][2] + dB[nt][2]);
            s[nt][3] = sigmoid_t(dA[nt][3] + dB[nt][3]);
            __half2 v0 = __floats2half2_rn(s[nt][0], s[nt][1]);
            __half2 v1 = __floats2half2_rn(s[nt][2], s[nt][3]);
            *(__half2*)(smem + hnb + hoff[nt][0]) = v0;
            *(__half2*)(smem + hnb + hoff[nt][1]) = v1;
            st_remote_u32(rem_b + hoff[nt][0], *(uint32_t*)&v0);
            st_remote_u32(rem_b + hoff[nt][1], *(uint32_t*)&v1);
        }
        MBAR_ARRIVE(mbar);
        MBAR_ARRIVE_REMOTE(rem_mbar);
        (void)loc_b;

        // output drain in the post-arrive shadow
        float* outp = outcta + (size_t)t * (Bdim * Hdim);
#pragma unroll
        for (int nt = 0; nt < 2; ++nt) {
            int o = o0l + nt * 8;
            *(float2*)&outp[(size_t)g * Hdim + o]       = make_float2(s[nt][0], s[nt][1]);
            *(float2*)&outp[(size_t)(g + 8) * Hdim + o] = make_float2(s[nt][2], s[nt][3]);
        }
    }

    // no CTA may exit while peer remote ops could be in flight
    CLUSTER_SYNC();
}

// ---------------------------------------------------------------------------
// Harness entry.
// Inputs: tokens(i32 2048x512), h0(f32 2048x256), emb(f32 64x256),
//         W(f32 256x512), b(f32 256).  Output: f32 (512,2048,256)
// ---------------------------------------------------------------------------
extern "C" void kernel_launch(void* const* d_in, const int* in_sizes, int n_in,
                              void* d_out, int out_size) {
    const int*   tokens = (const int*)d_in[0];
    const float* h0     = (const float*)d_in[1];
    const float* emb    = (const float*)d_in[2];
    const float* W      = (const float*)d_in[3];
    const float* bias   = (const float*)d_in[4];
    float*       out    = (float*)d_out;
    (void)in_sizes; (void)n_in; (void)out_size;

    cudaFuncSetAttribute(k_rnn, cudaFuncAttributeMaxDynamicSharedMemorySize, SMEM_TOTAL);
    k_rnn<<<(Bdim / NB) * CLU, NTH, SMEM_TOTAL>>>(tokens, h0, emb, W, bias, out);
}

// round 13
// speedup vs baseline: 1.4468x; 1.4468x over previous
#include <cuda_runtime.h>
#include <cuda_fp16.h>
#include <cstdint>

#define Hdim 256
#define Bdim 2048
#define Tdim 512
#define Vdim 64
#define NB   16          // batches per CTA -> 128 CTAs
#define NTH  512         // 16 warps, each owns 16 outputs (2 n8 tiles)
#define HSTR 264         // h row stride in halfs (528B)
#define PSTR 266         // P row stride in floats
#define ESTR 68          // embT row stride in floats

// ---- shared memory layout (bytes) ----
#define SM_P    0                      // P[64][PSTR] f32 = 68096
#define SM_H0   68096                  // h buf0: 16 x 264 halfs = 8448
#define SM_H1   76544                  // h buf1: 8448
#define SM_TOK  84992                  // tokens [512][16] int = 32768
#define SM_EMBT 117760                 // transient embT f32 [256][ESTR]
#define SMEM_TOTAL (117760 + 69632)    // 187392

// ---------------------------------------------------------------------------
__device__ __forceinline__ uint32_t smem_u32(const void* p) {
    uint32_t a;
    asm("{ .reg .u64 t; cvta.to.shared.u64 t, %1; cvt.u32.u64 %0, t; }"
        : "=r"(a) : "l"(p));
    return a;
}
// sigmoid via single-MUFU tanh: s = 0.5*tanh(0.5x) + 0.5
__device__ __forceinline__ float sigmoid_t(float x) {
    float t;
    asm("tanh.approx.f32 %0, %1;" : "=f"(t) : "f"(0.5f * x));
    return fmaf(0.5f, t, 0.5f);
}
__device__ __forceinline__ void ffma2(unsigned long long& d,
                                      unsigned long long a, unsigned long long b) {
    asm("fma.rn.f32x2 %0, %1, %2, %0;" : "+l"(d) : "l"(a), "l"(b));
}
__device__ __forceinline__ unsigned long long pack2(float lo, float hi) {
    unsigned long long r;
    asm("mov.b64 %0, {%1, %2};" : "=l"(r) : "f"(lo), "f"(hi));
    return r;
}
__device__ __forceinline__ void mma16816(float* d, const uint32_t* a,
                                         uint32_t b0, uint32_t b1) {
    asm volatile(
        "mma.sync.aligned.m16n8k16.row.col.f32.f16.f16.f32 "
        "{%0,%1,%2,%3}, {%4,%5,%6,%7}, {%8,%9}, {%0,%1,%2,%3};"
        : "+f"(d[0]), "+f"(d[1]), "+f"(d[2]), "+f"(d[3])
        : "r"(a[0]), "r"(a[1]), "r"(a[2]), "r"(a[3]), "r"(b0), "r"(b1));
}
__device__ __forceinline__ void ldmx4(uint32_t& r0, uint32_t& r1,
                                      uint32_t& r2, uint32_t& r3, uint32_t addr) {
    asm volatile(
        "ldmatrix.sync.aligned.m8n8.x4.shared.b16 {%0,%1,%2,%3}, [%4];"
        : "=r"(r0), "=r"(r1), "=r"(r2), "=r"(r3) : "r"(addr));
}

// ---------------------------------------------------------------------------
// Persistent RNN: CTA owns 16 batch chains for 512 steps.
// D[16 batch, 256 out] = h[16,256] x WhT; warp w owns outputs [16w, 16w+16)
// (2 n8 tiles, breg register-resident). One hardware __syncthreads per step
// (warp-granular arrive + broadcast release; drains STS natively). Shadow
// work preserved: step t's STG drains after the barrier (during step t+1's
// MMA), step t+1's P/token prefetch runs before the barrier. Accumulator
// chains split (dA: chunks 0-7, dB: 8-15) for HMMA ILP.
// ---------------------------------------------------------------------------
__global__ __launch_bounds__(NTH, 1)
void k_rnn(const int* __restrict__ tokens,
           const float* __restrict__ h0,
           const float* __restrict__ emb,
           const float* __restrict__ W,
           const float* __restrict__ bias,
           float* __restrict__ out) {
    extern __shared__ char smem[];
    const uint32_t sbase = smem_u32(smem);
    float* Psm  = (float*)(smem + SM_P);
    int*   toks = (int*)(smem + SM_TOK);

    const int tid  = threadIdx.x;
    const int wid  = tid >> 5;
    const int lane = tid & 31;
    const int g    = lane >> 2;     // 0..7
    const int r    = lane & 3;      // 0..3
    const int bbase = blockIdx.x * NB;

    // ============== Prologue ==============
    {
        float* embT = (float*)(smem + SM_EMBT);
        for (int idx = tid; idx < Vdim * Hdim; idx += NTH) {
            int v = idx >> 8, k = idx & 255;
            embT[(size_t)k * ESTR + v] = emb[(size_t)v * Hdim + k];
        }
    }
    __syncthreads();
    {   // P[v][o] = bias[o] + emb[v,:]·Wx[o,:]; thread: o = tid&255, 2 v-groups
        const float* embT = (const float*)(smem + SM_EMBT);
        const int o = tid & 255;
        const int vg0 = (tid >> 8) * 2;
        const float bo = bias[o];
        const float4* wrow = (const float4*)(W + (size_t)o * (2 * Hdim));
        for (int vg = vg0; vg < vg0 + 2; ++vg) {
            unsigned long long acc[8];
#pragma unroll
            for (int i = 0; i < 8; ++i) acc[i] = pack2(0.f, 0.f);
            for (int k4 = 0; k4 < Hdim / 4; ++k4) {
                float4 wv = wrow[k4];
#pragma unroll
                for (int kk = 0; kk < 4; ++kk) {
                    int k = k4 * 4 + kk;
                    float w = (kk == 0) ? wv.x : (kk == 1) ? wv.y : (kk == 2) ? wv.z : wv.w;
                    unsigned long long wpair = pack2(w, w);
                    const ulonglong2* ep =
                        (const ulonglong2*)(embT + (size_t)k * ESTR + vg * 16);
                    ulonglong2 e0 = ep[0], e1 = ep[1], e2 = ep[2], e3 = ep[3];
                    ffma2(acc[0], wpair, e0.x); ffma2(acc[1], wpair, e0.y);
                    ffma2(acc[2], wpair, e1.x); ffma2(acc[3], wpair, e1.y);
                    ffma2(acc[4], wpair, e2.x); ffma2(acc[5], wpair, e2.y);
                    ffma2(acc[6], wpair, e3.x); ffma2(acc[7], wpair, e3.y);
                }
            }
#pragma unroll
            for (int i = 0; i < 8; ++i) {
                float lo = __uint_as_float((uint32_t)(acc[i] & 0xffffffffu));
                float hi = __uint_as_float((uint32_t)(acc[i] >> 32));
                int v0 = vg * 16 + 2 * i;
                Psm[(size_t)v0 * PSTR + o]       = bo + lo;
                Psm[(size_t)(v0 + 1) * PSTR + o] = bo + hi;
            }
        }
    }
    // B fragments: warp owns outputs [16w, 16w+16) -> 2 n8 tiles
    uint32_t breg[2][16][2];
#pragma unroll
    for (int nt = 0; nt < 2; ++nt) {
        int n = wid * 16 + nt * 8 + g;
        const float* wr = W + (size_t)n * (2 * Hdim) + Hdim;
#pragma unroll
        for (int c = 0; c < 16; ++c) {
            float2 lo = *(const float2*)&wr[2 * r + 16 * c];
            float2 hi = *(const float2*)&wr[2 * r + 8 + 16 * c];
            __half2 hlo = __floats2half2_rn(lo.x, lo.y);
            __half2 hhi = __floats2half2_rn(hi.x, hi.y);
            breg[nt][c][0] = *(uint32_t*)&hlo;
            breg[nt][c][1] = *(uint32_t*)&hhi;
        }
    }
    for (int idx = tid; idx < NB * Tdim; idx += NTH) {
        int b = idx >> 9, t = idx & 511;
        toks[t * NB + b] = tokens[(size_t)(bbase + b) * Tdim + t];
    }
    {
        __half* hb = (__half*)(smem + SM_H0);
        for (int idx = tid; idx < NB * Hdim; idx += NTH) {
            int b = idx >> 8, k = idx & 255;
            hb[(size_t)b * HSTR + k] =
                __float2half_rn(h0[(size_t)(bbase + b) * Hdim + k]);
        }
    }
    __syncthreads();     // toks + h(0) published

    const uint32_t ldm_base =
        (uint32_t)((lane & 15) * (HSTR * 2) + (lane >> 4) * 16);
    const int o0 = wid * 16 + 2 * r;
    float* const outcta = out + (size_t)bbase * Hdim;

    // prefetch for t = 0
    float p[2][4];
    {
        const int tk0 = toks[g];
        const int tk1 = toks[g + 8];
#pragma unroll
        for (int nt = 0; nt < 2; ++nt) {
            float2 p0 = *(const float2*)&Psm[(size_t)tk0 * PSTR + o0 + nt * 8];
            float2 p1 = *(const float2*)&Psm[(size_t)tk1 * PSTR + o0 + nt * 8];
            p[nt][0] = p0.x; p[nt][1] = p0.y;
            p[nt][2] = p1.x; p[nt][3] = p1.y;
        }
    }
    float s[2][4];

    // ============== Recurrent loop ==============
    for (int t = 0; t < Tdim; ++t) {
        __syncthreads();             // h(t) visible (STS drained by BAR)

        // step t-1 output drain in the shadow of this step's MMA
        if (t > 0) {
            float* outp = outcta + (size_t)(t - 1) * (Bdim * Hdim);
#pragma unroll
            for (int nt = 0; nt < 2; ++nt) {
                int o = o0 + nt * 8;
                *(float2*)&outp[(size_t)g * Hdim + o] =
                    make_float2(s[nt][0], s[nt][1]);
                *(float2*)&outp[(size_t)(g + 8) * Hdim + o] =
                    make_float2(s[nt][2], s[nt][3]);
            }
        }

        // init accumulators from prefetched P; split chains dA/dB
        float dA[2][4], dB[2][4];
#pragma unroll
        for (int nt = 0; nt < 2; ++nt) {
            dA[nt][0] = p[nt][0]; dA[nt][1] = p[nt][1];
            dA[nt][2] = p[nt][2]; dA[nt][3] = p[nt][3];
            dB[nt][0] = 0.f; dB[nt][1] = 0.f;
            dB[nt][2] = 0.f; dB[nt][3] = 0.f;
        }

        const uint32_t abuf = sbase + ((t & 1) ? SM_H1 : SM_H0) + ldm_base;
#pragma unroll
        for (int cc = 0; cc < 8; ++cc) {
            uint32_t a0[4], a1[4];
            ldmx4(a0[0], a0[1], a0[2], a0[3], abuf + (uint32_t)cc * 32);
            ldmx4(a1[0], a1[1], a1[2], a1[3], abuf + (uint32_t)(cc + 8) * 32);
            mma16816(dA[0], a0, breg[0][cc][0], breg[0][cc][1]);
            mma16816(dB[0], a1, breg[0][cc + 8][0], breg[0][cc + 8][1]);
            mma16816(dA[1], a0, breg[1][cc][0], breg[1][cc][1]);
            mma16816(dB[1], a1, breg[1][cc + 8][0], breg[1][cc + 8][1]);
        }

        // fold chains, sigmoid, STS h(t+1)
        __half* hn = (__half*)(smem + ((t & 1) ? SM_H0 : SM_H1));
#pragma unroll
        for (int nt = 0; nt < 2; ++nt) {
            s[nt][0] = sigmoid_t(dA[nt][0] + dB[nt][0]);
            s[nt][1] = sigmoid_t(dA[nt][1] + dB[nt][1]);
            s[nt][2] = sigmoid_t(dA[nt][2] + dB[nt][2]);
            s[nt][3] = sigmoid_t(dA[nt][3] + dB[nt][3]);
            int o = o0 + nt * 8;
            *(__half2*)&hn[(size_t)g * HSTR + o] =
                __floats2half2_rn(s[nt][0], s[nt][1]);
            *(__half2*)&hn[(size_t)(g + 8) * HSTR + o] =
                __floats2half2_rn(s[nt][2], s[nt][3]);
        }

        // prefetch P/tokens for t+1 (stable regions; pre-barrier shadow)
        {
            const int tn = (t + 1) & 511;
            const int tk0 = toks[tn * NB + g];
            const int tk1 = toks[tn * NB + g + 8];
#pragma unroll
            for (int nt = 0; nt < 2; ++nt) {
                float2 p0 = *(const float2*)&Psm[(size_t)tk0 * PSTR + o0 + nt * 8];
                float2 p1 = *(const float2*)&Psm[(size_t)tk1 * PSTR + o0 + nt * 8];
                p[nt][0] = p0.x; p[nt][1] = p0.y;
                p[nt][2] = p1.x; p[nt][3] = p1.y;
            }
        }
    }

    // final output drain (step T-1)
    {
        float* outp = outcta + (size_t)(Tdim - 1) * (Bdim * Hdim);
#pragma unroll
        for (int nt = 0; nt < 2; ++nt) {
            int o = o0 + nt * 8;
            *(float2*)&outp[(size_t)g * Hdim + o] =
                make_float2(s[nt][0], s[nt][1]);
            *(float2*)&outp[(size_t)(g + 8) * Hdim + o] =
                make_float2(s[nt][2], s[nt][3]);
        }
    }
}

// ---------------------------------------------------------------------------
// Harness entry.
// Inputs: tokens(i32 2048x512), h0(f32 2048x256), emb(f32 64x256),
//         W(f32 256x512), b(f32 256).  Output: f32 (512,2048,256)
// ---------------------------------------------------------------------------
extern "C" void kernel_launch(void* const* d_in, const int* in_sizes, int n_in,
                              void* d_out, int out_size) {
    const int*   tokens = (const int*)d_in[0];
    const float* h0     = (const float*)d_in[1];
    const float* emb    = (const float*)d_in[2];
    const float* W      = (const float*)d_in[3];
    const float* bias   = (const float*)d_in[4];
    float*       out    = (float*)d_out;
    (void)in_sizes; (void)n_in; (void)out_size;

    cudaFuncSetAttribute(k_rnn, cudaFuncAttributeMaxDynamicSharedMemorySize, SMEM_TOTAL);
    k_rnn<<<Bdim / NB, NTH, SMEM_TOTAL>>>(tokens, h0, emb, W, bias, out);
}